// round 1
// baseline (speedup 1.0000x reference)
#include <cuda_runtime.h>
#include <cstdint>
#include <float.h>
#include <math.h>

#define Bn 8
#define Tn 4096
#define Dn 512
#define Rn 1024
#define T2 2048      // #src = #dst pairs
#define Cn 3072      // kept tokens = Tn - Rn

// ---------------- scratch (device globals; no allocation allowed) -------------
__device__ float g_inv[Bn * Tn];                 // 1/||x[b,t]||
__device__ float g_best[Bn * T2];                // best score per src
__device__ int   g_barg[Bn * T2];                // argmax dst (local 0..2047)
__device__ int   g_srctok[Bn * Rn];              // rank -> src token index
__device__ int   g_dsttok[Bn * Rn];              // rank -> dst token index
__device__ int   g_winner[Bn * T2];              // dst_local -> winning rank (max), -1 none
__device__ unsigned char g_merged[Bn * Tn];      // merged_away mask
__device__ int   g_col[Bn * Cn];                 // compact idx -> token
__device__ float g_A[(size_t)Bn * Cn * Dn];      // merged matrix (GEMM A), 48 MB

// ---------------- K1: inverse norms ----------------
__global__ void k_norms(const float* __restrict__ x) {
    int row = blockIdx.x * 8 + (threadIdx.x >> 5);
    int lane = threadIdx.x & 31;
    const float4* p = (const float4*)(x + (size_t)row * Dn);
    float ss = 0.f;
#pragma unroll
    for (int i = 0; i < 4; i++) {
        float4 v = p[lane + 32 * i];
        ss += v.x * v.x + v.y * v.y + v.z * v.z + v.w * v.w;
    }
#pragma unroll
    for (int o = 16; o; o >>= 1) ss += __shfl_xor_sync(0xFFFFFFFFu, ss, o);
    if (lane == 0) g_inv[row] = 1.0f / fmaxf(sqrtf(ss), 1e-12f);
}

// ---------------- K2: scores GEMM with fused row max/argmax ----------------
// Block: 64 src rows; loops all 2048 dst in 128-wide tiles; K tiled by 16.
__global__ __launch_bounds__(256) void k_scores(const float* __restrict__ x) {
    const int b  = blockIdx.y;
    const int m0 = blockIdx.x * 64;
    __shared__ float As[16][64];
    __shared__ float Bs[16][128];
    __shared__ float s_cn[128];
    __shared__ float s_max[64];
    __shared__ int   s_arg[64];

    const int tid = threadIdx.x;
    const int tx = tid & 15, ty = tid >> 4;
    if (tid < 64) { s_max[tid] = -FLT_MAX; s_arg[tid] = 0; }

    const float* xb = x + (size_t)b * Tn * Dn;
    const int a_r = tid >> 2;            // 0..63
    const int a_k = (tid & 3) * 4;
    const float* aptr = xb + (size_t)(2 * (m0 + a_r) + 1) * Dn + a_k;
    const int b_r = tid >> 2;            // 0..63, plus +64 row
    const int b_k = (tid & 3) * 4;

    float acc[4][8];

    for (int nt = 0; nt < 16; ++nt) {
        const int n0 = nt * 128;
        __syncthreads();                     // protect s_cn, s_max reads from prev iter
        if (tid < 128) s_cn[tid] = g_inv[b * Tn + 2 * (n0 + tid)];
#pragma unroll
        for (int i = 0; i < 4; i++)
#pragma unroll
            for (int j = 0; j < 8; j++) acc[i][j] = 0.f;

        const float* bptr = xb + (size_t)(2 * (n0 + b_r)) * Dn + b_k;

        for (int kt = 0; kt < Dn; kt += 16) {
            float4 av  = *(const float4*)(aptr + kt);
            float4 bv0 = *(const float4*)(bptr + kt);
            float4 bv1 = *(const float4*)(bptr + (size_t)128 * Dn + kt);
            __syncthreads();
            As[a_k + 0][a_r] = av.x;  As[a_k + 1][a_r] = av.y;
            As[a_k + 2][a_r] = av.z;  As[a_k + 3][a_r] = av.w;
            Bs[b_k + 0][b_r] = bv0.x; Bs[b_k + 1][b_r] = bv0.y;
            Bs[b_k + 2][b_r] = bv0.z; Bs[b_k + 3][b_r] = bv0.w;
            Bs[b_k + 0][b_r + 64] = bv1.x; Bs[b_k + 1][b_r + 64] = bv1.y;
            Bs[b_k + 2][b_r + 64] = bv1.z; Bs[b_k + 3][b_r + 64] = bv1.w;
            __syncthreads();
#pragma unroll
            for (int k = 0; k < 16; k++) {
                float4 a4 = *(const float4*)(&As[k][ty * 4]);
                float4 b0 = *(const float4*)(&Bs[k][tx * 8]);
                float4 b1 = *(const float4*)(&Bs[k][tx * 8 + 4]);
                float ar[4] = {a4.x, a4.y, a4.z, a4.w};
                float br[8] = {b0.x, b0.y, b0.z, b0.w, b1.x, b1.y, b1.z, b1.w};
#pragma unroll
                for (int i = 0; i < 4; i++)
#pragma unroll
                    for (int j = 0; j < 8; j++)
                        acc[i][j] = fmaf(ar[i], br[j], acc[i][j]);
            }
        }
        // scale by dst inv-norm, reduce max/argmax (first-occurrence ties)
#pragma unroll
        for (int i = 0; i < 4; i++) {
            float best = -FLT_MAX; int barg = 0x7FFFFFFF;
#pragma unroll
            for (int j = 0; j < 8; j++) {
                float v = acc[i][j] * s_cn[tx * 8 + j];
                int c = n0 + tx * 8 + j;
                if (v > best || (v == best && c < barg)) { best = v; barg = c; }
            }
#pragma unroll
            for (int o = 8; o; o >>= 1) {
                float ov = __shfl_xor_sync(0xFFFFFFFFu, best, o);
                int   oc = __shfl_xor_sync(0xFFFFFFFFu, barg, o);
                if (ov > best || (ov == best && oc < barg)) { best = ov; barg = oc; }
            }
            if (tx == 0) {
                int r = ty * 4 + i;
                if (best > s_max[r] || (best == s_max[r] && barg < s_arg[r])) {
                    s_max[r] = best; s_arg[r] = barg;
                }
            }
        }
    }
    __syncthreads();
    if (tid < 64) {
        int s = m0 + tid;
        g_best[b * T2 + s] = s_max[tid] * g_inv[b * Tn + 2 * s + 1];
        g_barg[b * T2 + s] = s_arg[tid];
    }
}

// ---------------- K3: per-batch bitonic sort -> top-k, winner, mask ----------------
__global__ void k_topk() {
    const int b = blockIdx.x;
    __shared__ unsigned long long keys[T2];
    const int tid = threadIdx.x; // 1024 threads
    g_winner[b * T2 + tid] = -1;
    g_winner[b * T2 + tid + 1024] = -1;
    for (int t = tid; t < Tn; t += 1024) g_merged[b * Tn + t] = 0;
    for (int i = tid; i < T2; i += 1024) {
        unsigned u = __float_as_uint(g_best[b * T2 + i]);
        u = (u & 0x80000000u) ? ~u : (u | 0x80000000u); // ascending-monotone
        u = ~u;                                          // descending score
        keys[i] = ((unsigned long long)u << 32) | (unsigned)i;
    }
    __syncthreads();
    for (int k2 = 2; k2 <= T2; k2 <<= 1) {
        for (int j = k2 >> 1; j > 0; j >>= 1) {
            for (int i = tid; i < T2; i += 1024) {
                int ixj = i ^ j;
                if (ixj > i) {
                    bool up = ((i & k2) == 0);
                    unsigned long long a = keys[i], c = keys[ixj];
                    if ((a > c) == up) { keys[i] = c; keys[ixj] = a; }
                }
            }
            __syncthreads();
        }
    }
    if (tid < Rn) {
        int s = (int)(keys[tid] & 0xFFFFFFFFu);
        int stok = 2 * s + 1;
        int dloc = g_barg[b * T2 + s];
        g_srctok[b * Rn + tid] = stok;
        g_dsttok[b * Rn + tid] = 2 * dloc;
        g_merged[b * Tn + stok] = 1;
        atomicMax(&g_winner[b * T2 + dloc], tid);  // last update (max rank) wins
    }
}

// ---------------- K4: compaction (stable argsort of mask) ----------------
__global__ void k_scan() {
    const int b = blockIdx.x;
    __shared__ int sums[1024];
    const int tid = threadIdx.x;
    const int base = tid * 4;
    int loc[4]; int c0 = 0;
#pragma unroll
    for (int i = 0; i < 4; i++) { loc[i] = g_merged[b * Tn + base + i] ? 0 : 1; c0 += loc[i]; }
    sums[tid] = c0; __syncthreads();
    for (int off = 1; off < 1024; off <<= 1) {
        int v = (tid >= off) ? sums[tid - off] : 0;
        __syncthreads();
        sums[tid] += v;
        __syncthreads();
    }
    int run = (tid == 0) ? 0 : sums[tid - 1];
#pragma unroll
    for (int i = 0; i < 4; i++) {
        if (loc[i]) { g_col[b * Cn + run] = base + i; run++; }
    }
}

// ---------------- K5: build merged A matrix ----------------
__global__ void k_build(const float* __restrict__ x) {
    const int b = blockIdx.y, c = blockIdx.x;
    const int t = g_col[b * Cn + c];
    const int tid = threadIdx.x; // 128
    const float* xb = x + (size_t)b * Tn * Dn;
    float4 v = *(const float4*)(xb + (size_t)t * Dn + tid * 4);
    if ((t & 1) == 0) {
        int w = g_winner[b * T2 + (t >> 1)];
        if (w >= 0) {
            int mt = g_srctok[b * Rn + w];
            float4 u = *(const float4*)(xb + (size_t)mt * Dn + tid * 4);
            v.x = (u.x + v.x) * 0.5f; v.y = (u.y + v.y) * 0.5f;
            v.z = (u.z + v.z) * 0.5f; v.w = (u.w + v.w) * 0.5f;
        }
    }
    *(float4*)(g_A + ((size_t)b * Cn + c) * Dn + tid * 4) = v;
}

// ---------------- K6: hidden = A @ W + bias, scattered to out rows ----------------
__global__ __launch_bounds__(256) void k_gemm(const float* __restrict__ W,
                                              const float* __restrict__ bias,
                                              float* __restrict__ out) {
    const int nt = blockIdx.x;     // 0..3 (N tiles of 128)
    const int mt = blockIdx.y;     // 0..191 (M tiles of 128)
    __shared__ float As[16][128];
    __shared__ float Bs[16][128];
    __shared__ float s_bias[128];
    __shared__ int   s_tok[128];

    const int tid = threadIdx.x;
    const int tx = tid & 15, ty = tid >> 4;
    const int m0 = mt * 128;
    const int b  = m0 / Cn;              // 3072 % 128 == 0: tile never crosses batch
    const int cm0 = m0 % Cn;
    if (tid < 128) {
        s_bias[tid] = bias[nt * 128 + tid];
        s_tok[tid]  = g_col[b * Cn + cm0 + tid];
    }
    const float* Abase = g_A + (size_t)m0 * Dn;
    const int a_r = tid >> 2, a_k = (tid & 3) * 4;
    const int w_r = tid >> 5, w_n = (tid & 31) * 4;

    float acc[8][8];
#pragma unroll
    for (int i = 0; i < 8; i++)
#pragma unroll
        for (int j = 0; j < 8; j++) acc[i][j] = 0.f;

    for (int kt = 0; kt < Dn; kt += 16) {
        float4 a0 = *(const float4*)(Abase + (size_t)a_r * Dn + kt + a_k);
        float4 a1 = *(const float4*)(Abase + (size_t)(a_r + 64) * Dn + kt + a_k);
        float4 w0 = *(const float4*)(W + (size_t)(kt + w_r) * Dn + nt * 128 + w_n);
        float4 w1 = *(const float4*)(W + (size_t)(kt + w_r + 8) * Dn + nt * 128 + w_n);
        __syncthreads();
        As[a_k + 0][a_r] = a0.x; As[a_k + 1][a_r] = a0.y;
        As[a_k + 2][a_r] = a0.z; As[a_k + 3][a_r] = a0.w;
        As[a_k + 0][a_r + 64] = a1.x; As[a_k + 1][a_r + 64] = a1.y;
        As[a_k + 2][a_r + 64] = a1.z; As[a_k + 3][a_r + 64] = a1.w;
        *(float4*)&Bs[w_r][w_n]     = w0;
        *(float4*)&Bs[w_r + 8][w_n] = w1;
        __syncthreads();
#pragma unroll
        for (int k = 0; k < 16; k++) {
            float4 av0 = *(const float4*)&As[k][ty * 8];
            float4 av1 = *(const float4*)&As[k][ty * 8 + 4];
            float4 bv0 = *(const float4*)&Bs[k][tx * 8];
            float4 bv1 = *(const float4*)&Bs[k][tx * 8 + 4];
            float ar[8] = {av0.x, av0.y, av0.z, av0.w, av1.x, av1.y, av1.z, av1.w};
            float br[8] = {bv0.x, bv0.y, bv0.z, bv0.w, bv1.x, bv1.y, bv1.z, bv1.w};
#pragma unroll
            for (int i = 0; i < 8; i++)
#pragma unroll
                for (int j = 0; j < 8; j++)
                    acc[i][j] = fmaf(ar[i], br[j], acc[i][j]);
        }
    }
    float* ob = out + (size_t)b * Tn * Dn + nt * 128;
#pragma unroll
    for (int i = 0; i < 8; i++) {
        int r = ty * 8 + i;
        int t = s_tok[r];
        float* op = ob + (size_t)t * Dn + tx * 8;
        float4 o0, o1;
        o0.x = acc[i][0] + s_bias[tx * 8 + 0]; o0.y = acc[i][1] + s_bias[tx * 8 + 1];
        o0.z = acc[i][2] + s_bias[tx * 8 + 2]; o0.w = acc[i][3] + s_bias[tx * 8 + 3];
        o1.x = acc[i][4] + s_bias[tx * 8 + 4]; o1.y = acc[i][5] + s_bias[tx * 8 + 5];
        o1.z = acc[i][6] + s_bias[tx * 8 + 6]; o1.w = acc[i][7] + s_bias[tx * 8 + 7];
        *(float4*)op       = o0;
        *(float4*)(op + 4) = o1;
    }
}

// ---------------- K7: out[src] = out[dst] ----------------
__global__ void k_copy(float* __restrict__ out) {
    const int b = blockIdx.y, i = blockIdx.x;
    const int st = g_srctok[b * Rn + i], dt = g_dsttok[b * Rn + i];
    const int tid = threadIdx.x; // 128
    const float4* src = (const float4*)(out + (size_t)b * Tn * Dn + (size_t)dt * Dn);
    float4* dst = (float4*)(out + (size_t)b * Tn * Dn + (size_t)st * Dn);
    dst[tid] = src[tid];
}

extern "C" void kernel_launch(void* const* d_in, const int* in_sizes, int n_in,
                              void* d_out, int out_size) {
    const float* x    = (const float*)d_in[0];
    const float* W    = (const float*)d_in[1];
    const float* bias = (const float*)d_in[2];
    float* out = (float*)d_out;

    k_norms<<<Bn * Tn / 8, 256>>>(x);
    dim3 g2(T2 / 64, Bn);
    k_scores<<<g2, 256>>>(x);
    k_topk<<<Bn, 1024>>>();
    k_scan<<<Bn, 1024>>>();
    dim3 g5(Cn, Bn);
    k_build<<<g5, 128>>>(x);
    dim3 g6(Dn / 128, (Bn * Cn) / 128);
    k_gemm<<<g6, 256>>>(W, bias, out);
    dim3 g7(Rn, Bn);
    k_copy<<<g7, 128>>>(out);
}

// round 2
// speedup vs baseline: 1.0013x; 1.0013x over previous
#include <cuda_runtime.h>
#include <cstdint>
#include <float.h>
#include <math.h>

#define Bn 8
#define Tn 4096
#define Dn 512
#define Rn 1024
#define T2 2048      // #src = #dst pairs
#define Cn 3072      // kept tokens = Tn - Rn

// ---------------- scratch (device globals; no allocation allowed) -------------
__device__ float g_inv[Bn * Tn];                 // 1/||x[b,t]||
__device__ float g_best[Bn * T2];                // best score per src
__device__ int   g_barg[Bn * T2];                // argmax dst (local 0..2047)
__device__ int   g_srctok[Bn * Rn];              // rank -> src token index
__device__ int   g_dsttok[Bn * Rn];              // rank -> dst token index
__device__ int   g_winner[Bn * T2];              // dst_local -> winning rank (max), -1 none
__device__ unsigned char g_merged[Bn * Tn];      // merged_away mask
__device__ int   g_col[Bn * Cn];                 // compact idx -> token
__device__ float g_A[(size_t)Bn * Cn * Dn];      // merged matrix (GEMM A), 48 MB

// ---------------- K1: inverse norms ----------------
__global__ void k_norms(const float* __restrict__ x) {
    int row = blockIdx.x * 8 + (threadIdx.x >> 5);
    int lane = threadIdx.x & 31;
    const float4* p = (const float4*)(x + (size_t)row * Dn);
    float ss = 0.f;
#pragma unroll
    for (int i = 0; i < 4; i++) {
        float4 v = p[lane + 32 * i];
        ss += v.x * v.x + v.y * v.y + v.z * v.z + v.w * v.w;
    }
#pragma unroll
    for (int o = 16; o; o >>= 1) ss += __shfl_xor_sync(0xFFFFFFFFu, ss, o);
    if (lane == 0) g_inv[row] = 1.0f / fmaxf(sqrtf(ss), 1e-12f);
}

// ---------------- K2: scores GEMM with fused row max/argmax ----------------
// Block: 64 src rows; loops all 2048 dst in 128-wide tiles; K tiled by 16.
__global__ __launch_bounds__(256) void k_scores(const float* __restrict__ x) {
    const int b  = blockIdx.y;
    const int m0 = blockIdx.x * 64;
    __shared__ float As[16][64];
    __shared__ float Bs[16][128];
    __shared__ float s_cn[128];
    __shared__ float s_max[64];
    __shared__ int   s_arg[64];

    const int tid = threadIdx.x;
    const int tx = tid & 15, ty = tid >> 4;
    if (tid < 64) { s_max[tid] = -FLT_MAX; s_arg[tid] = 0; }

    const float* xb = x + (size_t)b * Tn * Dn;
    const int a_r = tid >> 2;            // 0..63
    const int a_k = (tid & 3) * 4;
    const float* aptr = xb + (size_t)(2 * (m0 + a_r) + 1) * Dn + a_k;
    const int b_r = tid >> 2;            // 0..63, plus +64 row
    const int b_k = (tid & 3) * 4;

    float acc[4][8];

    for (int nt = 0; nt < 16; ++nt) {
        const int n0 = nt * 128;
        __syncthreads();                     // protect s_cn, s_max reads from prev iter
        if (tid < 128) s_cn[tid] = g_inv[b * Tn + 2 * (n0 + tid)];
#pragma unroll
        for (int i = 0; i < 4; i++)
#pragma unroll
            for (int j = 0; j < 8; j++) acc[i][j] = 0.f;

        const float* bptr = xb + (size_t)(2 * (n0 + b_r)) * Dn + b_k;

        for (int kt = 0; kt < Dn; kt += 16) {
            float4 av  = *(const float4*)(aptr + kt);
            float4 bv0 = *(const float4*)(bptr + kt);
            float4 bv1 = *(const float4*)(bptr + (size_t)128 * Dn + kt);
            __syncthreads();
            As[a_k + 0][a_r] = av.x;  As[a_k + 1][a_r] = av.y;
            As[a_k + 2][a_r] = av.z;  As[a_k + 3][a_r] = av.w;
            Bs[b_k + 0][b_r] = bv0.x; Bs[b_k + 1][b_r] = bv0.y;
            Bs[b_k + 2][b_r] = bv0.z; Bs[b_k + 3][b_r] = bv0.w;
            Bs[b_k + 0][b_r + 64] = bv1.x; Bs[b_k + 1][b_r + 64] = bv1.y;
            Bs[b_k + 2][b_r + 64] = bv1.z; Bs[b_k + 3][b_r + 64] = bv1.w;
            __syncthreads();
#pragma unroll
            for (int k = 0; k < 16; k++) {
                float4 a4 = *(const float4*)(&As[k][ty * 4]);
                float4 b0 = *(const float4*)(&Bs[k][tx * 8]);
                float4 b1 = *(const float4*)(&Bs[k][tx * 8 + 4]);
                float ar[4] = {a4.x, a4.y, a4.z, a4.w};
                float br[8] = {b0.x, b0.y, b0.z, b0.w, b1.x, b1.y, b1.z, b1.w};
#pragma unroll
                for (int i = 0; i < 4; i++)
#pragma unroll
                    for (int j = 0; j < 8; j++)
                        acc[i][j] = fmaf(ar[i], br[j], acc[i][j]);
            }
        }
        // scale by dst inv-norm, reduce max/argmax (first-occurrence ties)
#pragma unroll
        for (int i = 0; i < 4; i++) {
            float best = -FLT_MAX; int barg = 0x7FFFFFFF;
#pragma unroll
            for (int j = 0; j < 8; j++) {
                float v = acc[i][j] * s_cn[tx * 8 + j];
                int c = n0 + tx * 8 + j;
                if (v > best || (v == best && c < barg)) { best = v; barg = c; }
            }
#pragma unroll
            for (int o = 8; o; o >>= 1) {
                float ov = __shfl_xor_sync(0xFFFFFFFFu, best, o);
                int   oc = __shfl_xor_sync(0xFFFFFFFFu, barg, o);
                if (ov > best || (ov == best && oc < barg)) { best = ov; barg = oc; }
            }
            if (tx == 0) {
                int r = ty * 4 + i;
                if (best > s_max[r] || (best == s_max[r] && barg < s_arg[r])) {
                    s_max[r] = best; s_arg[r] = barg;
                }
            }
        }
    }
    __syncthreads();
    if (tid < 64) {
        int s = m0 + tid;
        g_best[b * T2 + s] = s_max[tid] * g_inv[b * Tn + 2 * s + 1];
        g_barg[b * T2 + s] = s_arg[tid];
    }
}

// ---------------- K3: per-batch bitonic sort -> top-k, winner, mask ----------------
__global__ void k_topk() {
    const int b = blockIdx.x;
    __shared__ unsigned long long keys[T2];
    const int tid = threadIdx.x; // 1024 threads
    g_winner[b * T2 + tid] = -1;
    g_winner[b * T2 + tid + 1024] = -1;
    for (int t = tid; t < Tn; t += 1024) g_merged[b * Tn + t] = 0;
    for (int i = tid; i < T2; i += 1024) {
        unsigned u = __float_as_uint(g_best[b * T2 + i]);
        u = (u & 0x80000000u) ? ~u : (u | 0x80000000u); // ascending-monotone
        u = ~u;                                          // descending score
        keys[i] = ((unsigned long long)u << 32) | (unsigned)i;
    }
    __syncthreads();
    for (int k2 = 2; k2 <= T2; k2 <<= 1) {
        for (int j = k2 >> 1; j > 0; j >>= 1) {
            for (int i = tid; i < T2; i += 1024) {
                int ixj = i ^ j;
                if (ixj > i) {
                    bool up = ((i & k2) == 0);
                    unsigned long long a = keys[i], c = keys[ixj];
                    if ((a > c) == up) { keys[i] = c; keys[ixj] = a; }
                }
            }
            __syncthreads();
        }
    }
    if (tid < Rn) {
        int s = (int)(keys[tid] & 0xFFFFFFFFu);
        int stok = 2 * s + 1;
        int dloc = g_barg[b * T2 + s];
        g_srctok[b * Rn + tid] = stok;
        g_dsttok[b * Rn + tid] = 2 * dloc;
        g_merged[b * Tn + stok] = 1;
        atomicMax(&g_winner[b * T2 + dloc], tid);  // last update (max rank) wins
    }
}

// ---------------- K4: compaction (stable argsort of mask) ----------------
__global__ void k_scan() {
    const int b = blockIdx.x;
    __shared__ int sums[1024];
    const int tid = threadIdx.x;
    const int base = tid * 4;
    int loc[4]; int c0 = 0;
#pragma unroll
    for (int i = 0; i < 4; i++) { loc[i] = g_merged[b * Tn + base + i] ? 0 : 1; c0 += loc[i]; }
    sums[tid] = c0; __syncthreads();
    for (int off = 1; off < 1024; off <<= 1) {
        int v = (tid >= off) ? sums[tid - off] : 0;
        __syncthreads();
        sums[tid] += v;
        __syncthreads();
    }
    int run = (tid == 0) ? 0 : sums[tid - 1];
#pragma unroll
    for (int i = 0; i < 4; i++) {
        if (loc[i]) { g_col[b * Cn + run] = base + i; run++; }
    }
}

// ---------------- K5: build merged A matrix ----------------
__global__ void k_build(const float* __restrict__ x) {
    const int b = blockIdx.y, c = blockIdx.x;
    const int t = g_col[b * Cn + c];
    const int tid = threadIdx.x; // 128
    const float* xb = x + (size_t)b * Tn * Dn;
    float4 v = *(const float4*)(xb + (size_t)t * Dn + tid * 4);
    if ((t & 1) == 0) {
        int w = g_winner[b * T2 + (t >> 1)];
        if (w >= 0) {
            int mt = g_srctok[b * Rn + w];
            float4 u = *(const float4*)(xb + (size_t)mt * Dn + tid * 4);
            v.x = (u.x + v.x) * 0.5f; v.y = (u.y + v.y) * 0.5f;
            v.z = (u.z + v.z) * 0.5f; v.w = (u.w + v.w) * 0.5f;
        }
    }
    *(float4*)(g_A + ((size_t)b * Cn + c) * Dn + tid * 4) = v;
}

// ---------------- K6: hidden = A @ W + bias, scattered to out rows ----------------
__global__ __launch_bounds__(256) void k_gemm(const float* __restrict__ W,
                                              const float* __restrict__ bias,
                                              float* __restrict__ out) {
    const int nt = blockIdx.x;     // 0..3 (N tiles of 128)
    const int mt = blockIdx.y;     // 0..191 (M tiles of 128)
    __shared__ float As[16][128];
    __shared__ float Bs[16][128];
    __shared__ float s_bias[128];
    __shared__ int   s_tok[128];

    const int tid = threadIdx.x;
    const int tx = tid & 15, ty = tid >> 4;
    const int m0 = mt * 128;
    const int b  = m0 / Cn;              // 3072 % 128 == 0: tile never crosses batch
    const int cm0 = m0 % Cn;
    if (tid < 128) {
        s_bias[tid] = bias[nt * 128 + tid];
        s_tok[tid]  = g_col[b * Cn + cm0 + tid];
    }
    const float* Abase = g_A + (size_t)m0 * Dn;
    const int a_r = tid >> 2, a_k = (tid & 3) * 4;
    const int w_r = tid >> 5, w_n = (tid & 31) * 4;

    float acc[8][8];
#pragma unroll
    for (int i = 0; i < 8; i++)
#pragma unroll
        for (int j = 0; j < 8; j++) acc[i][j] = 0.f;

    for (int kt = 0; kt < Dn; kt += 16) {
        float4 a0 = *(const float4*)(Abase + (size_t)a_r * Dn + kt + a_k);
        float4 a1 = *(const float4*)(Abase + (size_t)(a_r + 64) * Dn + kt + a_k);
        float4 w0 = *(const float4*)(W + (size_t)(kt + w_r) * Dn + nt * 128 + w_n);
        float4 w1 = *(const float4*)(W + (size_t)(kt + w_r + 8) * Dn + nt * 128 + w_n);
        __syncthreads();
        As[a_k + 0][a_r] = a0.x; As[a_k + 1][a_r] = a0.y;
        As[a_k + 2][a_r] = a0.z; As[a_k + 3][a_r] = a0.w;
        As[a_k + 0][a_r + 64] = a1.x; As[a_k + 1][a_r + 64] = a1.y;
        As[a_k + 2][a_r + 64] = a1.z; As[a_k + 3][a_r + 64] = a1.w;
        *(float4*)&Bs[w_r][w_n]     = w0;
        *(float4*)&Bs[w_r + 8][w_n] = w1;
        __syncthreads();
#pragma unroll
        for (int k = 0; k < 16; k++) {
            float4 av0 = *(const float4*)&As[k][ty * 8];
            float4 av1 = *(const float4*)&As[k][ty * 8 + 4];
            float4 bv0 = *(const float4*)&Bs[k][tx * 8];
            float4 bv1 = *(const float4*)&Bs[k][tx * 8 + 4];
            float ar[8] = {av0.x, av0.y, av0.z, av0.w, av1.x, av1.y, av1.z, av1.w};
            float br[8] = {bv0.x, bv0.y, bv0.z, bv0.w, bv1.x, bv1.y, bv1.z, bv1.w};
#pragma unroll
            for (int i = 0; i < 8; i++)
#pragma unroll
                for (int j = 0; j < 8; j++)
                    acc[i][j] = fmaf(ar[i], br[j], acc[i][j]);
        }
    }
    float* ob = out + (size_t)b * Tn * Dn + nt * 128;
#pragma unroll
    for (int i = 0; i < 8; i++) {
        int r = ty * 8 + i;
        int t = s_tok[r];
        float* op = ob + (size_t)t * Dn + tx * 8;
        float4 o0, o1;
        o0.x = acc[i][0] + s_bias[tx * 8 + 0]; o0.y = acc[i][1] + s_bias[tx * 8 + 1];
        o0.z = acc[i][2] + s_bias[tx * 8 + 2]; o0.w = acc[i][3] + s_bias[tx * 8 + 3];
        o1.x = acc[i][4] + s_bias[tx * 8 + 4]; o1.y = acc[i][5] + s_bias[tx * 8 + 5];
        o1.z = acc[i][6] + s_bias[tx * 8 + 6]; o1.w = acc[i][7] + s_bias[tx * 8 + 7];
        *(float4*)op       = o0;
        *(float4*)(op + 4) = o1;
    }
}

// ---------------- K7: out[src] = out[dst] ----------------
__global__ void k_copy(float* __restrict__ out) {
    const int b = blockIdx.y, i = blockIdx.x;
    const int st = g_srctok[b * Rn + i], dt = g_dsttok[b * Rn + i];
    const int tid = threadIdx.x; // 128
    const float4* src = (const float4*)(out + (size_t)b * Tn * Dn + (size_t)dt * Dn);
    float4* dst = (float4*)(out + (size_t)b * Tn * Dn + (size_t)st * Dn);
    dst[tid] = src[tid];
}

extern "C" void kernel_launch(void* const* d_in, const int* in_sizes, int n_in,
                              void* d_out, int out_size) {
    const float* x    = (const float*)d_in[0];
    const float* W    = (const float*)d_in[1];
    const float* bias = (const float*)d_in[2];
    float* out = (float*)d_out;

    k_norms<<<Bn * Tn / 8, 256>>>(x);
    dim3 g2(T2 / 64, Bn);
    k_scores<<<g2, 256>>>(x);
    k_topk<<<Bn, 1024>>>();
    k_scan<<<Bn, 1024>>>();
    dim3 g5(Cn, Bn);
    k_build<<<g5, 128>>>(x);
    dim3 g6(Dn / 128, (Bn * Cn) / 128);
    k_gemm<<<g6, 256>>>(W, bias, out);
    dim3 g7(Rn, Bn);
    k_copy<<<g7, 128>>>(out);
}